// round 10
// baseline (speedup 1.0000x reference)
#include <cuda_runtime.h>
#include <cstdint>

// ---------------------------------------------------------------------------
// fp4 (bitsandbytes) dequant + GEMV:  y[4, M] = x[4, N] @ W[M, N]^T + bias
//   qweight: numel/2 int32, each holding ONE byte (two nibbles, hi first)
//   absmax : per-64-element block scale; code: 16-entry codebook
//
// Single kernel. 512 blocks x 128 threads; warp owns 4 rows, full N.
// Per-warp cp.async pipeline for the q stream: 8-deep ring of 512B stages
// (4 rows x 32 int32) in smem, LDGSTS so q-DRAM latency never touches the
// register scoreboard. absmax preloaded to smem per warp. x read as LDG.64
// lane-consecutive (L1-resident: 128KB reused by all blocks). Decode via
// register-resident 16-entry codebook + __shfl. Packed f32x2 FMAs.
// No __syncthreads in the main loop (warp-private pipeline), no 2nd kernel.
// ---------------------------------------------------------------------------

constexpr int MD = 8192, ND = 8192;
constexpr int RW  = 4;                  // rows per warp
constexpr int WPB = 4;                  // warps per block (128 threads)
constexpr int RPB = RW * WPB;           // 16 rows per block
constexpr int STAGES = ND / 64;         // 128 stages of 64 n
constexpr int DEPTH  = 8;               // pipeline depth (stages in flight)

static __device__ __forceinline__ unsigned long long pk2(float lo, float hi) {
    unsigned long long r;
    asm("mov.b64 %0, {%1, %2};" : "=l"(r) : "f"(lo), "f"(hi));
    return r;
}
static __device__ __forceinline__ void up2(unsigned long long v, float& lo, float& hi) {
    asm("mov.b64 {%0, %1}, %2;" : "=f"(lo), "=f"(hi) : "l"(v));
}
static __device__ __forceinline__ unsigned long long f2fma(unsigned long long a,
                                                           unsigned long long b,
                                                           unsigned long long c) {
    unsigned long long d;
    asm("fma.rn.f32x2 %0, %1, %2, %3;" : "=l"(d) : "l"(a), "l"(b), "l"(c));
    return d;
}
static __device__ __forceinline__ unsigned long long f2add(unsigned long long a,
                                                           unsigned long long b) {
    unsigned long long d;
    asm("add.rn.f32x2 %0, %1, %2;" : "=l"(d) : "l"(a), "l"(b));
    return d;
}
static __device__ __forceinline__ uint32_t s2u(const void* p) {
    uint32_t a;
    asm("{.reg .u64 t; cvta.to.shared.u64 t, %1; cvt.u32.u64 %0, t;}" : "=r"(a) : "l"(p));
    return a;
}
static __device__ __forceinline__ void cp16(uint32_t dst, const void* src) {
    asm volatile("cp.async.cg.shared.global [%0], [%1], 16;"
                 :: "r"(dst), "l"(src) : "memory");
}
static __device__ __forceinline__ void cp_commit() {
    asm volatile("cp.async.commit_group;" ::: "memory");
}
static __device__ __forceinline__ void cp_wait6() {
    asm volatile("cp.async.wait_group 6;" ::: "memory");
}

__global__ void __launch_bounds__(128, 4)
fp4_main(const float* __restrict__ x, const int* __restrict__ qw,
         const float* __restrict__ am, const float* __restrict__ code,
         const float* __restrict__ bias, float* __restrict__ out)
{
    // q ring: [warp][slot][row 0..3][32 int32]  -> 4*8*4*32 ints = 16 KB
    __shared__ int   q_sm[WPB * DEPTH * RW * 32];
    // absmax:  [warp*4 + row][stage]            -> 16*128 floats = 8 KB
    __shared__ float am_sm[RPB * STAGES];

    const int lane = threadIdx.x & 31;
    const int wid  = threadIdx.x >> 5;
    const int row0 = blockIdx.x * RPB + wid * RW;

    // Register-resident codebook: lane l holds code[l & 15]; decode via shfl.
    const float creg = code[lane & 15];

    // ---- absmax preload (per warp, its own 4 rows; 128 floats each) ----
#pragma unroll
    for (int r = 0; r < RW; r++) {
        const float4 v = __ldg(reinterpret_cast<const float4*>(
                                   am + (row0 + r) * (ND / 64)) + lane);
        reinterpret_cast<float4*>(&am_sm[(wid * RW + r) * STAGES])[lane] = v;
    }
    __syncwarp();

    // ---- per-lane cp.async source/dest mapping ----
    // Lane l copies 16B of row (l>>3), words (l&7)*4 .. +3, per stage.
    const int lr = lane >> 3;            // 0..3 (row within warp)
    const int lc = lane & 7;             // 0..7 (16B chunk within 128B row seg)
    const int* qsrc = qw + (row0 + lr) * (ND / 2) + lc * 4;
    const uint32_t qdst0 = s2u(q_sm)
        + (uint32_t)(((wid * DEPTH) * RW + lr) * 32 + lc * 4) * 4u;
    // slot s adds s * (RW*32*4) = s * 512 bytes.

    // x streams (lane-consecutive LDG.64).
    const float2* x0 = reinterpret_cast<const float2*>(x + 0 * ND);
    const float2* x1 = reinterpret_cast<const float2*>(x + 1 * ND);
    const float2* x2 = reinterpret_cast<const float2*>(x + 2 * ND);
    const float2* x3 = reinterpret_cast<const float2*>(x + 3 * ND);

    // ---- pipeline prologue: stages 0 .. DEPTH-2 ----
#pragma unroll
    for (int s = 0; s < DEPTH - 1; s++) {
        cp16(qdst0 + s * 512u, qsrc + s * 32);
        cp_commit();
    }

    unsigned long long a01[RW] = {0, 0, 0, 0};
    unsigned long long a23[RW] = {0, 0, 0, 0};

    const uint32_t qrd0 = s2u(q_sm) + (uint32_t)((wid * DEPTH * RW) * 32 + lane) * 4u;

#pragma unroll 2
    for (int j = 0; j < STAGES; ++j) {
        cp_wait6();            // stage j complete (DEPTH-2 groups may be pending)
        __syncwarp();          // cross-lane smem visibility + WAR ordering

        const int col  = j * 32 + lane;
        const int slot = j & (DEPTH - 1);

        const float2 v0 = __ldg(&x0[col]);
        const float2 v1 = __ldg(&x1[col]);
        const float2 v2 = __ldg(&x2[col]);
        const float2 v3 = __ldg(&x3[col]);
        const unsigned long long xe01 = pk2(v0.x, v1.x);
        const unsigned long long xo01 = pk2(v0.y, v1.y);
        const unsigned long long xe23 = pk2(v2.x, v3.x);
        const unsigned long long xo23 = pk2(v2.y, v3.y);

#pragma unroll
        for (int r = 0; r < RW; r++) {
            int b;
            asm("ld.shared.b32 %0, [%1];" : "=r"(b)
                : "r"(qrd0 + (uint32_t)(slot * 512 + r * 128)));
            const float s = am_sm[(wid * RW + r) * STAGES + j];   // uniform
            const float chi = __shfl_sync(0xffffffffu, creg, b >> 4);
            const float clo = __shfl_sync(0xffffffffu, creg, b & 15);
            const float w0 = chi * s;
            const float w1 = clo * s;
            const unsigned long long s0 = pk2(w0, w0);
            const unsigned long long s1 = pk2(w1, w1);
            a01[r] = f2fma(s0, xe01, a01[r]);
            a01[r] = f2fma(s1, xo01, a01[r]);
            a23[r] = f2fma(s0, xe23, a23[r]);
            a23[r] = f2fma(s1, xo23, a23[r]);
        }

        // Refill: issue stage j+DEPTH-1 into slot (j-1)%DEPTH (consumed at
        // iter j-1; the syncwarp above orders those reads before this write).
        const int s_iss = j + DEPTH - 1;
        if (s_iss < STAGES) {
            cp16(qdst0 + (uint32_t)((s_iss & (DEPTH - 1)) * 512), qsrc + s_iss * 32);
        }
        cp_commit();           // always commit (possibly empty group)
    }

    // Butterfly reduction over lanes (packed f32x2 adds).
#pragma unroll
    for (int r = 0; r < RW; r++) {
#pragma unroll
        for (int off = 16; off > 0; off >>= 1) {
            a01[r] = f2add(a01[r], __shfl_xor_sync(0xffffffffu, a01[r], off));
            a23[r] = f2add(a23[r], __shfl_xor_sync(0xffffffffu, a23[r], off));
        }
    }

#pragma unroll
    for (int r = 0; r < RW; r++) {
        if (lane == r) {
            const int row = row0 + r;
            float y0, y1, y2, y3;
            up2(a01[r], y0, y1);
            up2(a23[r], y2, y3);
            const float bb = bias[row];
            out[0 * MD + row] = y0 + bb;
            out[1 * MD + row] = y1 + bb;
            out[2 * MD + row] = y2 + bb;
            out[3 * MD + row] = y3 + bb;
        }
    }
}

extern "C" void kernel_launch(void* const* d_in, const int* in_sizes, int n_in,
                              void* d_out, int out_size)
{
    const float* x    = (const float*)d_in[0];
    const int*   qw   = (const int*)d_in[1];
    const float* am   = (const float*)d_in[2];
    const float* code = (const float*)d_in[3];
    const float* bias = (const float*)d_in[4];
    float*       out  = (float*)d_out;

    fp4_main<<<MD / RPB, WPB * 32>>>(x, qw, am, code, bias, out);
}

// round 11
// speedup vs baseline: 1.2469x; 1.2469x over previous
#include <cuda_runtime.h>
#include <cstdint>

// ---------------------------------------------------------------------------
// fp4 (bitsandbytes) dequant + GEMV:  y[4, M] = x[4, N] @ W[M, N]^T + bias
//   qweight: numel/2 int32, each holding ONE byte (two nibbles, hi first)
//   absmax : per-64-element block scale; code: 16-entry codebook
//
// R5 mapping (best measured): warp owns a contiguous 64-n "step"; lane l
// takes the packed byte at int32 index (step*32 + l), i.e. n = 2l, 2l+1.
// R11 changes:
//   * q prefetch distance 1 in registers (keeps 4 q-LDGs in flight per warp
//     continuously instead of ~1 -> in-flight bytes ~4x)
//   * q loaded with __ldcs (streaming, evict-first: protects L1-resident x)
//   * absmax preloaded to smem per block (uniform LDS broadcast in loop)
//   * __launch_bounds__(128,7): <=72 regs, 7 CTAs/SM -> all 1024 blocks in
//     ONE wave (1036 slots), 28 warps/SM.
// 4 rows/warp, 4 warps/block, N split in 2; tiny deterministic reduce.
// ---------------------------------------------------------------------------

constexpr int MD = 8192, ND = 8192;
constexpr int NSPLIT = 2;
constexpr int NHALF  = ND / NSPLIT;     // 4096 n per block
constexpr int STEPS  = NHALF / 64;      // 64 steps (one absmax block each)
constexpr int RW = 4;                   // rows per warp
constexpr int WPB = 4;                  // warps per block (128 threads)
constexpr int RPB = RW * WPB;           // 16 rows per block

__device__ float g_part[NSPLIT * 4 * MD];   // [split][batch][row]

static __device__ __forceinline__ unsigned long long pk2(float lo, float hi) {
    unsigned long long r;
    asm("mov.b64 %0, {%1, %2};" : "=l"(r) : "f"(lo), "f"(hi));
    return r;
}
static __device__ __forceinline__ void up2(unsigned long long v, float& lo, float& hi) {
    asm("mov.b64 {%0, %1}, %2;" : "=f"(lo), "=f"(hi) : "l"(v));
}
static __device__ __forceinline__ unsigned long long f2fma(unsigned long long a,
                                                           unsigned long long b,
                                                           unsigned long long c) {
    unsigned long long d;
    asm("fma.rn.f32x2 %0, %1, %2, %3;" : "=l"(d) : "l"(a), "l"(b), "l"(c));
    return d;
}
static __device__ __forceinline__ unsigned long long f2add(unsigned long long a,
                                                           unsigned long long b) {
    unsigned long long d;
    asm("add.rn.f32x2 %0, %1, %2;" : "=l"(d) : "l"(a), "l"(b));
    return d;
}

__global__ void __launch_bounds__(128, 7)
fp4_main(const float* __restrict__ x, const int* __restrict__ qw,
         const float* __restrict__ am, const float* __restrict__ code)
{
    __shared__ float am_sm[RPB * STEPS];   // [row-in-block][step], 4 KB

    const int lane = threadIdx.x & 31;
    const int wid  = threadIdx.x >> 5;
    const int split   = blockIdx.x;            // 0 or 1
    const int rowbase = blockIdx.y * RPB;
    const int row0    = rowbase + wid * RW;
    const int n0      = split * NHALF;

    // Register-resident codebook: lane l holds code[l & 15]; decode via shfl.
    const float creg = code[lane & 15];

    // ---- absmax preload: RPB*STEPS = 1024 floats, coalesced ----
    for (int k = threadIdx.x; k < RPB * STEPS; k += 128) {
        const int r  = k >> 6;          // row in block
        const int st = k & 63;          // step
        am_sm[k] = am[(rowbase + r) * (ND / 64) + split * (NHALF / 64) + st];
    }
    __syncthreads();

    // Per-row q streams for this N-half.
    const int* q0 = qw + row0 * (ND / 2) + split * (NHALF / 2);
    const float2* x0 = reinterpret_cast<const float2*>(x + 0 * ND + n0);
    const float2* x1 = reinterpret_cast<const float2*>(x + 1 * ND + n0);
    const float2* x2 = reinterpret_cast<const float2*>(x + 2 * ND + n0);
    const float2* x3 = reinterpret_cast<const float2*>(x + 3 * ND + n0);

    unsigned long long a01[RW] = {0, 0, 0, 0};
    unsigned long long a23[RW] = {0, 0, 0, 0};

    // ---- q prefetch, distance 1 ----
    int bq[RW];
#pragma unroll
    for (int r = 0; r < RW; r++) bq[r] = __ldcs(q0 + r * (ND / 2) + lane);

#pragma unroll 2
    for (int step = 0; step < STEPS; ++step) {
        // Prefetch next step's q bytes (clamped on last iter; redundant load).
        const int ncol = (step < STEPS - 1 ? step + 1 : step) * 32 + lane;
        int bn[RW];
#pragma unroll
        for (int r = 0; r < RW; r++) bn[r] = __ldcs(q0 + r * (ND / 2) + ncol);

        const int col = step * 32 + lane;
        const float2 v0 = __ldg(&x0[col]);
        const float2 v1 = __ldg(&x1[col]);
        const float2 v2 = __ldg(&x2[col]);
        const float2 v3 = __ldg(&x3[col]);
        const unsigned long long xe01 = pk2(v0.x, v1.x);   // n even, batches 0,1
        const unsigned long long xo01 = pk2(v0.y, v1.y);   // n odd
        const unsigned long long xe23 = pk2(v2.x, v3.x);
        const unsigned long long xo23 = pk2(v2.y, v3.y);

#pragma unroll
        for (int r = 0; r < RW; r++) {
            const int   b = bq[r];                                  // one byte
            const float s = am_sm[(wid * RW + r) * STEPS + step];   // uniform LDS
            const float chi = __shfl_sync(0xffffffffu, creg, b >> 4);   // n = 2l
            const float clo = __shfl_sync(0xffffffffu, creg, b & 15);   // n = 2l+1
            const float w0 = chi * s;
            const float w1 = clo * s;
            const unsigned long long s0 = pk2(w0, w0);
            const unsigned long long s1 = pk2(w1, w1);
            a01[r] = f2fma(s0, xe01, a01[r]);
            a01[r] = f2fma(s1, xo01, a01[r]);
            a23[r] = f2fma(s0, xe23, a23[r]);
            a23[r] = f2fma(s1, xo23, a23[r]);
        }

#pragma unroll
        for (int r = 0; r < RW; r++) bq[r] = bn[r];
    }

    // Butterfly reduction over lanes (packed f32x2 adds).
#pragma unroll
    for (int r = 0; r < RW; r++) {
#pragma unroll
        for (int off = 16; off > 0; off >>= 1) {
            a01[r] = f2add(a01[r], __shfl_xor_sync(0xffffffffu, a01[r], off));
            a23[r] = f2add(a23[r], __shfl_xor_sync(0xffffffffu, a23[r], off));
        }
    }

#pragma unroll
    for (int r = 0; r < RW; r++) {
        if (lane == r) {
            const int row = row0 + r;
            float y0, y1, y2, y3;
            up2(a01[r], y0, y1);
            up2(a23[r], y2, y3);
            g_part[(split * 4 + 0) * MD + row] = y0;
            g_part[(split * 4 + 1) * MD + row] = y1;
            g_part[(split * 4 + 2) * MD + row] = y2;
            g_part[(split * 4 + 3) * MD + row] = y3;
        }
    }
}

__global__ void __launch_bounds__(256)
fp4_reduce(const float* __restrict__ bias, float* __restrict__ out)
{
    // i4 indexes groups of 4 consecutive outputs (same batch, consecutive rows).
    const int i4 = blockIdx.x * 256 + threadIdx.x;
    if (i4 >= (4 * MD) / 4) return;
    const int i   = i4 * 4;
    const int row = i & (MD - 1);
    const float4 p0 = *reinterpret_cast<const float4*>(g_part + 0 * 4 * MD + i);
    const float4 p1 = *reinterpret_cast<const float4*>(g_part + 1 * 4 * MD + i);
    const float4 bb = *reinterpret_cast<const float4*>(bias + row);
    float4 o;
    o.x = p0.x + p1.x + bb.x;
    o.y = p0.y + p1.y + bb.y;
    o.z = p0.z + p1.z + bb.z;
    o.w = p0.w + p1.w + bb.w;
    *reinterpret_cast<float4*>(out + i) = o;
}

extern "C" void kernel_launch(void* const* d_in, const int* in_sizes, int n_in,
                              void* d_out, int out_size)
{
    const float* x    = (const float*)d_in[0];
    const int*   qw   = (const int*)d_in[1];
    const float* am   = (const float*)d_in[2];
    const float* code = (const float*)d_in[3];
    const float* bias = (const float*)d_in[4];
    float*       out  = (float*)d_out;

    dim3 grid(NSPLIT, MD / RPB);              // (2, 512) = 1024 blocks
    fp4_main<<<grid, WPB * 32>>>(x, qw, am, code);
    fp4_reduce<<<((4 * MD) / 4 + 255) / 256, 256>>>(bias, out);
}